// round 12
// baseline (speedup 1.0000x reference)
#include <cuda_runtime.h>

// SymbolSubcarrierAutocorrelation — Round 12: 4 column-pairs per thread + global ED scratch.
//   * 4 pair-threads/tile (8 output columns each): per-tile smem delivery for the
//     dominant stage-2/3 broadcasts halves (the invariant is bytes RECEIVED per thread).
//   * E/D streamed to __device__ scratch per s-group (no 40-float register carry,
//     no smem union barrier dance); __syncthreads() gives within-block visibility.
//   * Stages 3+4 fused per-thread (t2 never touches smem). v0 column on 32 clean threads.

#define SDIM 5
#define WDIM 33
#define ADIM 16
#define NPAIR 16
#define TPB 32
#define PAIRT (TPB * 4)         // 128 pair-threads
#define THREADS (PAIRT + TPB)   // 160
#define MAXTILES 65536
#define EDSTRIDE 192            // floats per tile: 16 w-slots x 12 (E0..3|D0..3|E4,D4,pad)

__device__ __align__(16) float g_ed[MAXTILES * EDSTRIDE];   // ~50 MB static scratch

// One stage-2 pass over NS symbol rows starting at s0. Computes X for the thread's
// 4 column-pairs (fwd+mirror), then E/D, streaming them to scratch.
template<int NS>
__device__ __forceinline__ void stage2_pass(
    const float4* __restrict__ sdTile,   // &sSD[ts*NPAIR*SDIM]
    const float2* __restrict__ t10sm,    // &sT10[ts][0]
    const float2* u1, const float2* ra, float k, int s0,
    float* edBase, int q)
{
    float Xr[4][NS][2], Xi[4][NS][2];
    #pragma unroll
    for (int ss = 0; ss < NS; ss++) {
        const float2 t10 = t10sm[s0 + ss];          // LDS broadcast
        const float br = k * t10.x, bi = k * t10.y;
        #pragma unroll
        for (int p = 0; p < 4; p++) {
            Xr[p][ss][0] = br; Xr[p][ss][1] = br;
            Xi[p][ss][0] = bi; Xi[p][ss][1] = bi;
        }
    }
    float2 fa[4];
    #pragma unroll
    for (int p = 0; p < 4; p++) fa[p] = u1[p];

    #pragma unroll 4
    for (int w = 0; w < NPAIR; w++) {
        float4 sd[NS];
        #pragma unroll
        for (int ss = 0; ss < NS; ss++) sd[ss] = sdTile[w * SDIM + s0 + ss];
        #pragma unroll
        for (int p = 0; p < 4; p++) {
            const float c = fa[p].x, si = fa[p].y;
            #pragma unroll
            for (int ss = 0; ss < NS; ss++) {
                const float pa = c * sd[ss].x, pb = si * sd[ss].w;
                const float pc_ = c * sd[ss].y, pd = si * sd[ss].z;
                Xr[p][ss][0] += pa - pb;  Xi[p][ss][0] += pc_ + pd;
                Xr[p][ss][1] += pa + pb;  Xi[p][ss][1] += pc_ - pd;
            }
            fa[p] = make_float2(fa[p].x * ra[p].x - fa[p].y * ra[p].y,
                                fa[p].x * ra[p].y + fa[p].y * ra[p].x);
        }
    }
    #pragma unroll
    for (int p = 0; p < 4; p++) {
        const int wp = 4 * q + p;                   // pair index this thread owns
        #pragma unroll
        for (int ss = 0; ss < NS; ss++) {
            const int s = s0 + ss;
            const float Pv = Xr[p][ss][0]*Xr[p][ss][0] + Xi[p][ss][0]*Xi[p][ss][0];
            const float Pm = Xr[p][ss][1]*Xr[p][ss][1] + Xi[p][ss][1]*Xi[p][ss][1];
            const int eo = (s < 4) ? s     : 8;
            const int dn = (s < 4) ? 4 + s : 9;
            edBase[wp * 12 + eo] = Pv + Pm;         // E
            edBase[wp * 12 + dn] = Pv - Pm;         // D
        }
    }
}

__global__ __launch_bounds__(THREADS, 4)
void autocorr_kernel(const float* __restrict__ xr, const float* __restrict__ xi,
                     const float* __restrict__ fsA, const float* __restrict__ fsB,
                     const float* __restrict__ fwA, const float* __restrict__ fwB,
                     float* __restrict__ outf,
                     int total_tiles,
                     unsigned int xcount,
                     unsigned int out_limit,
                     int real_only)
{
    __shared__ float4 sSD[TPB * NPAIR * SDIM];      // 40960 B
    __shared__ float2 sT10[TPB][SDIM];              // 1280 B
    __shared__ float  sP0 [TPB][SDIM];              // 640 B

    const int tid = threadIdx.x;

    const bool swSub = (fabsf(fwA[0]) < 1e-3f);
    const bool swSym = (fabsf(fsA[0]) < 1e-3f);
    const float* __restrict__ fwr = swSub ? fwB : fwA;
    const float* __restrict__ fwi = swSub ? fwA : fwB;
    const float* __restrict__ fsr = swSym ? fsB : fsA;
    const float* __restrict__ fsi = swSym ? fsA : fsB;

    const float k = fwr[0];                         // 1/sqrt(33)
    const float invk = 1.0f / k;

    float zr[SDIM], zi[SDIM];                       // F_sym[s][t] = z[(s*t)%5]
    #pragma unroll
    for (int q2 = 0; q2 < SDIM; q2++) { zr[q2] = fsr[SDIM + q2]; zi[q2] = fsi[SDIM + q2]; }

    const bool isV0 = (tid >= PAIRT);
    int ts, q;
    if (isV0) { ts = tid - PAIRT; q = 0; }
    else      { ts = tid >> 2;    q = tid & 3; }
    int tile = blockIdx.x * TPB + ts;
    if (tile >= total_tiles) tile = 0;
    if (tile >= MAXTILES) tile = 0;                 // scratch capacity guard
    const int n = tile >> 4;                        // ADIM == 16
    const int a = tile & 15;
    const unsigned int rowbase0 = (((unsigned int)n * SDIM) * ADIM + a) * WDIM;
    float* const edBase = g_ed + (size_t)tile * EDSTRIDE;
    const float4* const sdTile = &sSD[ts * NPAIR * SDIM];

    float2 u1[4], ra[4];                            // twiddle seeds for owned columns
    if (!isV0) {
        #pragma unroll
        for (int p = 0; p < 4; p++) {
            const int c = 4 * q + 1 + p;
            u1[p] = make_float2(fwr[WDIM + c], fwi[WDIM + c]);
            ra[p] = make_float2(u1[p].x * invk, u1[p].y * invk);
        }
    }

    float t10v[2 * SDIM];                           // v0 keeps its T1 row locally
    // ---- Stage 1 ----
    if (!isV0) {
        #pragma unroll
        for (int p = 0; p < 4; p++) {
            const int v = 4 * q + 1 + p;
            const int vm = WDIM - v;
            float2 xa[SDIM], xb[SDIM];
            #pragma unroll
            for (int t = 0; t < SDIM; t++) {
                unsigned int base = rowbase0 + (unsigned int)t * (ADIM * WDIM);
                unsigned int iA = base + v;  if (iA >= xcount) iA = 0;
                unsigned int iB = base + vm; if (iB >= xcount) iB = 0;
                xa[t] = make_float2(xr[iA], xi[iA]);
                xb[t] = make_float2(xr[iB], xi[iB]);
            }
            #pragma unroll
            for (int s = 0; s < SDIM; s++) {
                float Ar = 0.f, Ai = 0.f, Br = 0.f, Bi = 0.f;
                #pragma unroll
                for (int t = 0; t < SDIM; t++) {
                    const int I = (s * t) % SDIM;
                    const float cr = zr[I], ci = zi[I];
                    Ar += cr * xa[t].x - ci * xa[t].y;
                    Ai += cr * xa[t].y + ci * xa[t].x;
                    Br += cr * xb[t].x - ci * xb[t].y;
                    Bi += cr * xb[t].y + ci * xb[t].x;
                }
                sSD[(ts * NPAIR + (v - 1)) * SDIM + s] =
                    make_float4(Ar + Br, Ai + Bi, Ar - Br, Ai - Bi);
            }
        }
    } else {
        float2 x0[SDIM];
        #pragma unroll
        for (int t = 0; t < SDIM; t++) {
            unsigned int iA = rowbase0 + (unsigned int)t * (ADIM * WDIM);
            if (iA >= xcount) iA = 0;
            x0[t] = make_float2(xr[iA], xi[iA]);
        }
        #pragma unroll
        for (int s = 0; s < SDIM; s++) {
            float Ar = 0.f, Ai = 0.f;
            #pragma unroll
            for (int t = 0; t < SDIM; t++) {
                const int I = (s * t) % SDIM;
                Ar += zr[I] * x0[t].x - zi[I] * x0[t].y;
                Ai += zr[I] * x0[t].y + zi[I] * x0[t].x;
            }
            t10v[2 * s] = Ar; t10v[2 * s + 1] = Ai;
            sT10[ts][s] = make_float2(Ar, Ai);
        }
    }
    __syncthreads();

    // ---- Stage 2 ----
    float P0v[SDIM];                                // v0 keeps P0 locally
    if (!isV0) {
        stage2_pass<2>(sdTile, &sT10[ts][0], u1, ra, k, 0, edBase, q);
        stage2_pass<2>(sdTile, &sT10[ts][0], u1, ra, k, 2, edBase, q);
        stage2_pass<1>(sdTile, &sT10[ts][0], u1, ra, k, 4, edBase, q);
    } else {
        float sr[SDIM] = {0,0,0,0,0}, sm[SDIM] = {0,0,0,0,0};
        #pragma unroll 4
        for (int w = 0; w < NPAIR; w++) {
            #pragma unroll
            for (int s = 0; s < SDIM; s++) {
                const float2 sv = *reinterpret_cast<const float2*>(
                    &sSD[(ts * NPAIR + w) * SDIM + s]);
                sr[s] += sv.x;  sm[s] += sv.y;
            }
        }
        #pragma unroll
        for (int s = 0; s < SDIM; s++) {
            const float X0r = k * (t10v[2 * s]     + sr[s]);
            const float X0i = k * (t10v[2 * s + 1] + sm[s]);
            P0v[s] = X0r * X0r + X0i * X0i;
            sP0[ts][s] = P0v[s];
        }
    }
    __syncthreads();                                // scratch + sP0 visible in-block

    // ---- Stages 3 + 4 ----
    if (!isV0) {
        float t2r[4][SDIM], t2i[4][SDIM];
        #pragma unroll
        for (int s = 0; s < SDIM; s++) {
            const float b = k * sP0[ts][s];
            #pragma unroll
            for (int p = 0; p < 4; p++) { t2r[p][s] = b; t2i[p][s] = 0.f; }
        }
        float2 fa[4];
        #pragma unroll
        for (int p = 0; p < 4; p++) fa[p] = u1[p];

        #pragma unroll 4
        for (int w = 0; w < NPAIR; w++) {
            const float4 E4 = *reinterpret_cast<const float4*>(edBase + w * 12);
            const float4 D4 = *reinterpret_cast<const float4*>(edBase + w * 12 + 4);
            const float2 eD = *reinterpret_cast<const float2*>(edBase + w * 12 + 8);
            #pragma unroll
            for (int p = 0; p < 4; p++) {
                const float c = fa[p].x, si = fa[p].y;
                t2r[p][0] += E4.x * c;  t2i[p][0] -= D4.x * si;
                t2r[p][1] += E4.y * c;  t2i[p][1] -= D4.y * si;
                t2r[p][2] += E4.z * c;  t2i[p][2] -= D4.z * si;
                t2r[p][3] += E4.w * c;  t2i[p][3] -= D4.w * si;
                t2r[p][4] += eD.x * c;  t2i[p][4] -= eD.y * si;
                fa[p] = make_float2(fa[p].x * ra[p].x - fa[p].y * ra[p].y,
                                    fa[p].x * ra[p].y + fa[p].y * ra[p].x);
            }
        }
        #pragma unroll
        for (int p = 0; p < 4; p++) {
            const int v = 4 * q + 1 + p;
            #pragma unroll
            for (int sp = 0; sp < SDIM; sp++) {
                float yr = 0.f, yi = 0.f;
                #pragma unroll
                for (int s = 0; s < SDIM; s++) {
                    const int I = (s * sp) % SDIM;
                    yr += zr[I] * t2r[p][s] + zi[I] * t2i[p][s];
                    yi += zr[I] * t2i[p][s] - zi[I] * t2r[p][s];
                }
                unsigned int oidx = (((unsigned int)n * SDIM + sp) * ADIM + a) * WDIM + v;
                const int sp2 = (SDIM - sp) % SDIM;
                unsigned int midx = (((unsigned int)n * SDIM + sp2) * ADIM + a) * WDIM + (WDIM - v);
                if (real_only) {
                    if (oidx < out_limit) outf[oidx] = yr;
                    if (midx < out_limit) outf[midx] = yr;
                } else {
                    if (2u * oidx + 1u < out_limit)
                        reinterpret_cast<float2*>(outf)[oidx] = make_float2(yr, yi);
                    if (2u * midx + 1u < out_limit)
                        reinterpret_cast<float2*>(outf)[midx] = make_float2(yr, -yi);
                }
            }
        }
    } else {
        float accE[SDIM] = {0,0,0,0,0};
        #pragma unroll 4
        for (int w = 0; w < NPAIR; w++) {
            const float4 E4 = *reinterpret_cast<const float4*>(edBase + w * 12);
            const float2 eD = *reinterpret_cast<const float2*>(edBase + w * 12 + 8);
            accE[0] += E4.x; accE[1] += E4.y; accE[2] += E4.z; accE[3] += E4.w;
            accE[4] += eD.x;
        }
        float t2r0[SDIM];
        #pragma unroll
        for (int s = 0; s < SDIM; s++)
            t2r0[s] = k * (P0v[s] + accE[s]);
        #pragma unroll
        for (int sp = 0; sp < SDIM; sp++) {
            float yr = 0.f, yi = 0.f;
            #pragma unroll
            for (int s = 0; s < SDIM; s++) {
                const int I = (s * sp) % SDIM;
                yr += zr[I] * t2r0[s];
                yi -= zi[I] * t2r0[s];
            }
            unsigned int oidx = (((unsigned int)n * SDIM + sp) * ADIM + a) * WDIM;
            if (real_only) {
                if (oidx < out_limit) outf[oidx] = yr;
            } else {
                if (2u * oidx + 1u < out_limit)
                    reinterpret_cast<float2*>(outf)[oidx] = make_float2(yr, yi);
            }
        }
    }
}

extern "C" void kernel_launch(void* const* d_in, const int* in_sizes, int n_in,
                              void* d_out, int out_size)
{
    long long big_raw = -1;
    for (int i = 0; i < n_in; i++)
        if ((long long)in_sizes[i] > big_raw) big_raw = in_sizes[i];

    const float *xr = 0, *xi = 0, *fsA = 0, *fsB = 0, *fwA = 0, *fwB = 0;
    int nsym = 0, nsub = 0, nbig = 0;
    for (int i = 0; i < n_in; i++) {
        const float* p = (const float*)d_in[i];
        long long c = in_sizes[i];
        if (c == SDIM * SDIM) {
            if (nsym++ == 0) fsA = p; else if (!fsB) fsB = p;
        } else if (c == WDIM * WDIM) {
            if (nsub++ == 0) fwA = p; else if (!fwB) fwB = p;
        } else if (c == big_raw) {
            if (nbig++ == 0) xr = p; else if (!xi) xi = p;
        }
    }
    if (!xr || !xi || !fsA || !fsB || !fwA || !fwB) return;

    const long long C = big_raw;
    const int N = (int)(C / (SDIM * ADIM * WDIM));
    const int total_tiles = N * ADIM;
    if (total_tiles <= 0) return;
    const int blocks = (total_tiles + TPB - 1) / TPB;

    const int real_only = ((long long)out_size >= 2 * C) ? 0 : 1;

    autocorr_kernel<<<blocks, THREADS>>>(
        xr, xi, fsA, fsB, fwA, fwB, (float*)d_out, total_tiles,
        (unsigned int)C, (unsigned int)out_size, real_only);
}

// round 13
// speedup vs baseline: 1.1146x; 1.1146x over previous
#include <cuda_runtime.h>

// SymbolSubcarrierAutocorrelation — Round 13: R12's 4-pairs-per-thread consumer
// halving + R11's smem exchange (global ED scratch was the R12 mistake: +L2 39%).
//   * TPB=24 tiles/block -> sSD + separate sED fit in 47.5KB static smem, no union
//   * 96 pair-threads (4 pairs = 8 columns each), 24 v0-threads, 8 idle pad
//   * E/D: 24-float register carry across the two s-passes, then 3 STS.128/pair

#define SDIM 5
#define WDIM 33
#define ADIM 16
#define NPAIR 16
#define TPB 24
#define PAIRT (TPB * 4)          // 96 pair-threads
#define V0T   TPB                // 24 v0-threads
#define THREADS 128              // 96 + 24 + 8 idle pad

__global__ __launch_bounds__(THREADS, 4)
void autocorr_kernel(const float* __restrict__ xr, const float* __restrict__ xi,
                     const float* __restrict__ fsA, const float* __restrict__ fsB,
                     const float* __restrict__ fwA, const float* __restrict__ fwB,
                     float* __restrict__ outf,
                     int total_tiles,
                     unsigned int xcount,
                     unsigned int out_limit,
                     int real_only)
{
    __shared__ float4 sSD [TPB * NPAIR * SDIM];     // 30720 B  (Sr,Si,Dr,Di)
    __shared__ float4 sEDa[TPB * NPAIR];            //  6144 B  E0..3
    __shared__ float4 sEDb[TPB * NPAIR];            //  6144 B  D0..3
    __shared__ float2 sEDc[TPB * NPAIR];            //  3072 B  (E4,D4)
    __shared__ float2 sT10[TPB][SDIM];              //   960 B
    __shared__ float  sP0 [TPB][SDIM];              //   480 B   => 47520 B total

    const int tid = threadIdx.x;

    const bool swSub = (fabsf(fwA[0]) < 1e-3f);
    const bool swSym = (fabsf(fsA[0]) < 1e-3f);
    const float* __restrict__ fwr = swSub ? fwB : fwA;
    const float* __restrict__ fwi = swSub ? fwA : fwB;
    const float* __restrict__ fsr = swSym ? fsB : fsA;
    const float* __restrict__ fsi = swSym ? fsA : fsB;

    const float k = fwr[0];                         // 1/sqrt(33)
    const float invk = 1.0f / k;

    float zr[SDIM], zi[SDIM];                       // F_sym[s][t] = z[(s*t)%5]
    #pragma unroll
    for (int q2 = 0; q2 < SDIM; q2++) { zr[q2] = fsr[SDIM + q2]; zi[q2] = fsi[SDIM + q2]; }

    const bool isPair = (tid < PAIRT);
    const bool isV0   = (tid >= PAIRT) && (tid < PAIRT + V0T);
    int ts = 0, q = 0;
    if (isPair)      { ts = tid >> 2;    q = tid & 3; }
    else if (isV0)   { ts = tid - PAIRT; }
    int tile = blockIdx.x * TPB + ts;
    if (tile >= total_tiles) tile = 0;
    const int n = tile >> 4;                        // ADIM == 16
    const int a = tile & 15;
    const unsigned int rowbase0 = (((unsigned int)n * SDIM) * ADIM + a) * WDIM;

    float2 u1[4], ra[4];                            // twiddle seeds for owned columns
    if (isPair) {
        #pragma unroll
        for (int p = 0; p < 4; p++) {
            const int c = 4 * q + 1 + p;
            u1[p] = make_float2(fwr[WDIM + c], fwi[WDIM + c]);
            ra[p] = make_float2(u1[p].x * invk, u1[p].y * invk);
        }
    }

    float t10v[2 * SDIM];                           // v0 keeps its T1 row locally
    // ---- Stage 1 ----
    if (isPair) {
        #pragma unroll
        for (int p = 0; p < 4; p++) {
            const int v = 4 * q + 1 + p;
            const int vm = WDIM - v;
            float2 xa[SDIM], xb[SDIM];
            #pragma unroll
            for (int t = 0; t < SDIM; t++) {
                unsigned int base = rowbase0 + (unsigned int)t * (ADIM * WDIM);
                unsigned int iA = base + v;  if (iA >= xcount) iA = 0;
                unsigned int iB = base + vm; if (iB >= xcount) iB = 0;
                xa[t] = make_float2(xr[iA], xi[iA]);
                xb[t] = make_float2(xr[iB], xi[iB]);
            }
            #pragma unroll
            for (int s = 0; s < SDIM; s++) {
                float Ar = 0.f, Ai = 0.f, Br = 0.f, Bi = 0.f;
                #pragma unroll
                for (int t = 0; t < SDIM; t++) {
                    const int I = (s * t) % SDIM;
                    const float cr = zr[I], ci = zi[I];
                    Ar += cr * xa[t].x - ci * xa[t].y;
                    Ai += cr * xa[t].y + ci * xa[t].x;
                    Br += cr * xb[t].x - ci * xb[t].y;
                    Bi += cr * xb[t].y + ci * xb[t].x;
                }
                sSD[(ts * NPAIR + (v - 1)) * SDIM + s] =
                    make_float4(Ar + Br, Ai + Bi, Ar - Br, Ai - Bi);
            }
        }
    } else if (isV0) {
        float2 x0[SDIM];
        #pragma unroll
        for (int t = 0; t < SDIM; t++) {
            unsigned int iA = rowbase0 + (unsigned int)t * (ADIM * WDIM);
            if (iA >= xcount) iA = 0;
            x0[t] = make_float2(xr[iA], xi[iA]);
        }
        #pragma unroll
        for (int s = 0; s < SDIM; s++) {
            float Ar = 0.f, Ai = 0.f;
            #pragma unroll
            for (int t = 0; t < SDIM; t++) {
                const int I = (s * t) % SDIM;
                Ar += zr[I] * x0[t].x - zi[I] * x0[t].y;
                Ai += zr[I] * x0[t].y + zi[I] * x0[t].x;
            }
            t10v[2 * s] = Ar; t10v[2 * s + 1] = Ai;
            sT10[ts][s] = make_float2(Ar, Ai);
        }
    }
    __syncthreads();

    // ---- Stage 2: two s-passes, E/D carried in regs, published to sED ----
    float P0v[SDIM];
    if (isPair) {
        const float4* const sdTile = &sSD[ts * NPAIR * SDIM];
        float Ecar[4][3], Dcar[4][3];               // s = 0..2 carry

        // Pass 1: s = 0,1,2
        {
            float Xr[4][3][2], Xi[4][3][2];
            #pragma unroll
            for (int ss = 0; ss < 3; ss++) {
                const float2 t10 = sT10[ts][ss];
                const float br = k * t10.x, bi = k * t10.y;
                #pragma unroll
                for (int p = 0; p < 4; p++) {
                    Xr[p][ss][0] = br; Xr[p][ss][1] = br;
                    Xi[p][ss][0] = bi; Xi[p][ss][1] = bi;
                }
            }
            float2 fa[4];
            #pragma unroll
            for (int p = 0; p < 4; p++) fa[p] = u1[p];
            #pragma unroll 4
            for (int w = 0; w < NPAIR; w++) {
                float4 sd[3];
                #pragma unroll
                for (int ss = 0; ss < 3; ss++) sd[ss] = sdTile[w * SDIM + ss];
                #pragma unroll
                for (int p = 0; p < 4; p++) {
                    const float c = fa[p].x, si = fa[p].y;
                    #pragma unroll
                    for (int ss = 0; ss < 3; ss++) {
                        const float pa = c * sd[ss].x, pb = si * sd[ss].w;
                        const float pc_ = c * sd[ss].y, pd = si * sd[ss].z;
                        Xr[p][ss][0] += pa - pb;  Xi[p][ss][0] += pc_ + pd;
                        Xr[p][ss][1] += pa + pb;  Xi[p][ss][1] += pc_ - pd;
                    }
                    fa[p] = make_float2(fa[p].x * ra[p].x - fa[p].y * ra[p].y,
                                        fa[p].x * ra[p].y + fa[p].y * ra[p].x);
                }
            }
            #pragma unroll
            for (int p = 0; p < 4; p++) {
                #pragma unroll
                for (int ss = 0; ss < 3; ss++) {
                    const float Pv = Xr[p][ss][0]*Xr[p][ss][0] + Xi[p][ss][0]*Xi[p][ss][0];
                    const float Pm = Xr[p][ss][1]*Xr[p][ss][1] + Xi[p][ss][1]*Xi[p][ss][1];
                    Ecar[p][ss] = Pv + Pm;  Dcar[p][ss] = Pv - Pm;
                }
            }
        }
        // Pass 2: s = 3,4; then publish
        {
            float Xr[4][2][2], Xi[4][2][2];
            #pragma unroll
            for (int ss = 0; ss < 2; ss++) {
                const float2 t10 = sT10[ts][3 + ss];
                const float br = k * t10.x, bi = k * t10.y;
                #pragma unroll
                for (int p = 0; p < 4; p++) {
                    Xr[p][ss][0] = br; Xr[p][ss][1] = br;
                    Xi[p][ss][0] = bi; Xi[p][ss][1] = bi;
                }
            }
            float2 fa[4];
            #pragma unroll
            for (int p = 0; p < 4; p++) fa[p] = u1[p];
            #pragma unroll 4
            for (int w = 0; w < NPAIR; w++) {
                float4 sd[2];
                #pragma unroll
                for (int ss = 0; ss < 2; ss++) sd[ss] = sdTile[w * SDIM + 3 + ss];
                #pragma unroll
                for (int p = 0; p < 4; p++) {
                    const float c = fa[p].x, si = fa[p].y;
                    #pragma unroll
                    for (int ss = 0; ss < 2; ss++) {
                        const float pa = c * sd[ss].x, pb = si * sd[ss].w;
                        const float pc_ = c * sd[ss].y, pd = si * sd[ss].z;
                        Xr[p][ss][0] += pa - pb;  Xi[p][ss][0] += pc_ + pd;
                        Xr[p][ss][1] += pa + pb;  Xi[p][ss][1] += pc_ - pd;
                    }
                    fa[p] = make_float2(fa[p].x * ra[p].x - fa[p].y * ra[p].y,
                                        fa[p].x * ra[p].y + fa[p].y * ra[p].x);
                }
            }
            #pragma unroll
            for (int p = 0; p < 4; p++) {
                float E3, D3, E4, D4;
                {
                    const float Pv = Xr[p][0][0]*Xr[p][0][0] + Xi[p][0][0]*Xi[p][0][0];
                    const float Pm = Xr[p][0][1]*Xr[p][0][1] + Xi[p][0][1]*Xi[p][0][1];
                    E3 = Pv + Pm;  D3 = Pv - Pm;
                }
                {
                    const float Pv = Xr[p][1][0]*Xr[p][1][0] + Xi[p][1][0]*Xi[p][1][0];
                    const float Pm = Xr[p][1][1]*Xr[p][1][1] + Xi[p][1][1]*Xi[p][1][1];
                    E4 = Pv + Pm;  D4 = Pv - Pm;
                }
                const int wp = ts * NPAIR + 4 * q + p;
                sEDa[wp] = make_float4(Ecar[p][0], Ecar[p][1], Ecar[p][2], E3);
                sEDb[wp] = make_float4(Dcar[p][0], Dcar[p][1], Dcar[p][2], D3);
                sEDc[wp] = make_float2(E4, D4);
            }
        }
    } else if (isV0) {
        float sr[SDIM] = {0,0,0,0,0}, sm[SDIM] = {0,0,0,0,0};
        #pragma unroll 4
        for (int w = 0; w < NPAIR; w++) {
            #pragma unroll
            for (int s = 0; s < SDIM; s++) {
                const float2 sv = *reinterpret_cast<const float2*>(
                    &sSD[(ts * NPAIR + w) * SDIM + s]);
                sr[s] += sv.x;  sm[s] += sv.y;
            }
        }
        #pragma unroll
        for (int s = 0; s < SDIM; s++) {
            const float X0r = k * (t10v[2 * s]     + sr[s]);
            const float X0i = k * (t10v[2 * s + 1] + sm[s]);
            P0v[s] = X0r * X0r + X0i * X0i;
            sP0[ts][s] = P0v[s];
        }
    }
    __syncthreads();

    // ---- Stages 3 + 4 ----
    if (isPair) {
        float t2r[4][SDIM], t2i[4][SDIM];
        #pragma unroll
        for (int s = 0; s < SDIM; s++) {
            const float b = k * sP0[ts][s];
            #pragma unroll
            for (int p = 0; p < 4; p++) { t2r[p][s] = b; t2i[p][s] = 0.f; }
        }
        float2 fa[4];
        #pragma unroll
        for (int p = 0; p < 4; p++) fa[p] = u1[p];
        #pragma unroll 4
        for (int w = 0; w < NPAIR; w++) {
            const float4 E4 = sEDa[ts * NPAIR + w];
            const float4 D4 = sEDb[ts * NPAIR + w];
            const float2 eD = sEDc[ts * NPAIR + w];
            #pragma unroll
            for (int p = 0; p < 4; p++) {
                const float c = fa[p].x, si = fa[p].y;
                t2r[p][0] += E4.x * c;  t2i[p][0] -= D4.x * si;
                t2r[p][1] += E4.y * c;  t2i[p][1] -= D4.y * si;
                t2r[p][2] += E4.z * c;  t2i[p][2] -= D4.z * si;
                t2r[p][3] += E4.w * c;  t2i[p][3] -= D4.w * si;
                t2r[p][4] += eD.x * c;  t2i[p][4] -= eD.y * si;
                fa[p] = make_float2(fa[p].x * ra[p].x - fa[p].y * ra[p].y,
                                    fa[p].x * ra[p].y + fa[p].y * ra[p].x);
            }
        }
        #pragma unroll
        for (int p = 0; p < 4; p++) {
            const int v = 4 * q + 1 + p;
            #pragma unroll
            for (int sp = 0; sp < SDIM; sp++) {
                float yr = 0.f, yi = 0.f;
                #pragma unroll
                for (int s = 0; s < SDIM; s++) {
                    const int I = (s * sp) % SDIM;
                    yr += zr[I] * t2r[p][s] + zi[I] * t2i[p][s];
                    yi += zr[I] * t2i[p][s] - zi[I] * t2r[p][s];
                }
                unsigned int oidx = (((unsigned int)n * SDIM + sp) * ADIM + a) * WDIM + v;
                const int sp2 = (SDIM - sp) % SDIM;
                unsigned int midx = (((unsigned int)n * SDIM + sp2) * ADIM + a) * WDIM + (WDIM - v);
                if (real_only) {
                    if (oidx < out_limit) outf[oidx] = yr;
                    if (midx < out_limit) outf[midx] = yr;
                } else {
                    if (2u * oidx + 1u < out_limit)
                        reinterpret_cast<float2*>(outf)[oidx] = make_float2(yr, yi);
                    if (2u * midx + 1u < out_limit)
                        reinterpret_cast<float2*>(outf)[midx] = make_float2(yr, -yi);
                }
            }
        }
    } else if (isV0) {
        float accE[SDIM] = {0,0,0,0,0};
        #pragma unroll 4
        for (int w = 0; w < NPAIR; w++) {
            const float4 E4 = sEDa[ts * NPAIR + w];
            const float2 eD = sEDc[ts * NPAIR + w];
            accE[0] += E4.x; accE[1] += E4.y; accE[2] += E4.z; accE[3] += E4.w;
            accE[4] += eD.x;
        }
        float t2r0[SDIM];
        #pragma unroll
        for (int s = 0; s < SDIM; s++)
            t2r0[s] = k * (P0v[s] + accE[s]);
        #pragma unroll
        for (int sp = 0; sp < SDIM; sp++) {
            float yr = 0.f, yi = 0.f;
            #pragma unroll
            for (int s = 0; s < SDIM; s++) {
                const int I = (s * sp) % SDIM;
                yr += zr[I] * t2r0[s];
                yi -= zi[I] * t2r0[s];
            }
            unsigned int oidx = (((unsigned int)n * SDIM + sp) * ADIM + a) * WDIM;
            if (real_only) {
                if (oidx < out_limit) outf[oidx] = yr;
            } else {
                if (2u * oidx + 1u < out_limit)
                    reinterpret_cast<float2*>(outf)[oidx] = make_float2(yr, yi);
            }
        }
    }
}

extern "C" void kernel_launch(void* const* d_in, const int* in_sizes, int n_in,
                              void* d_out, int out_size)
{
    long long big_raw = -1;
    for (int i = 0; i < n_in; i++)
        if ((long long)in_sizes[i] > big_raw) big_raw = in_sizes[i];

    const float *xr = 0, *xi = 0, *fsA = 0, *fsB = 0, *fwA = 0, *fwB = 0;
    int nsym = 0, nsub = 0, nbig = 0;
    for (int i = 0; i < n_in; i++) {
        const float* p = (const float*)d_in[i];
        long long c = in_sizes[i];
        if (c == SDIM * SDIM) {
            if (nsym++ == 0) fsA = p; else if (!fsB) fsB = p;
        } else if (c == WDIM * WDIM) {
            if (nsub++ == 0) fwA = p; else if (!fwB) fwB = p;
        } else if (c == big_raw) {
            if (nbig++ == 0) xr = p; else if (!xi) xi = p;
        }
    }
    if (!xr || !xi || !fsA || !fsB || !fwA || !fwB) return;

    const long long C = big_raw;
    const int N = (int)(C / (SDIM * ADIM * WDIM));
    const int total_tiles = N * ADIM;
    if (total_tiles <= 0) return;
    const int blocks = (total_tiles + TPB - 1) / TPB;

    const int real_only = ((long long)out_size >= 2 * C) ? 0 : 1;

    autocorr_kernel<<<blocks, THREADS>>>(
        xr, xi, fsA, fsB, fwA, fwB, (float*)d_out, total_tiles,
        (unsigned int)C, (unsigned int)out_size, real_only);
}